// round 6
// baseline (speedup 1.0000x reference)
#include <cuda_runtime.h>
#include <cuda_bf16.h>
#include <cstdint>

#define B_ 2
#define T_ 2048
#define HID_ 2048
#define NH_ 16
#define KVH_ 4
#define HD_ 128
#define K3 (3 * HID_)   // 6144

typedef __nv_bfloat16 bf16;

// fp32 GEMM outputs
__device__ float g_q[(size_t)B_ * T_ * NH_ * HD_];    // [4096][2048]
__device__ float g_kv[(size_t)B_ * T_ * 1024];        // [4096][1024] = K | V
// triple-split GEMM inputs: A row-major [m][3K], B transposed [n][3K]
__device__ bf16 g_hid_i[(size_t)4096 * K3];
__device__ bf16 g_ctx_i[(size_t)4096 * K3];           // written by flash epilogue
__device__ bf16 g_wq_t[(size_t)2048 * K3];
__device__ bf16 g_wkv_t[(size_t)1024 * K3];
__device__ bf16 g_wo_t[(size_t)2048 * K3];
// flash hi/lo inputs
__device__ bf16 g_qh[(size_t)B_ * T_ * NH_ * HD_];
__device__ bf16 g_ql[(size_t)B_ * T_ * NH_ * HD_];
__device__ bf16 g_kh[(size_t)B_ * T_ * KVH_ * HD_];
__device__ bf16 g_kl[(size_t)B_ * T_ * KVH_ * HD_];
__device__ bf16 g_vh[(size_t)B_ * T_ * KVH_ * HD_];
__device__ bf16 g_vl[(size_t)B_ * T_ * KVH_ * HD_];

// ---------------------------------------------------------------------------
// helpers (portable ISA only)
// ---------------------------------------------------------------------------
__device__ __forceinline__ void cp16(uint32_t s, const void* g) {
    asm volatile("cp.async.cg.shared.global [%0], [%1], 16;\n" :: "r"(s), "l"(g));
}
__device__ __forceinline__ void cp_commit() {
    asm volatile("cp.async.commit_group;\n" ::);
}
__device__ __forceinline__ void mma16816(float* c, const uint32_t* a, const uint32_t* b) {
    asm volatile(
        "mma.sync.aligned.m16n8k16.row.col.f32.bf16.bf16.f32 "
        "{%0,%1,%2,%3}, {%4,%5,%6,%7}, {%8,%9}, {%0,%1,%2,%3};\n"
        : "+f"(c[0]), "+f"(c[1]), "+f"(c[2]), "+f"(c[3])
        : "r"(a[0]), "r"(a[1]), "r"(a[2]), "r"(a[3]), "r"(b[0]), "r"(b[1]));
}
__device__ __forceinline__ void ldsm4(uint32_t* d, uint32_t addr) {
    asm volatile("ldmatrix.sync.aligned.m8n8.x4.shared.b16 {%0,%1,%2,%3}, [%4];\n"
                 : "=r"(d[0]), "=r"(d[1]), "=r"(d[2]), "=r"(d[3]) : "r"(addr));
}
__device__ __forceinline__ void ldsm4t(uint32_t* d, uint32_t addr) {
    asm volatile("ldmatrix.sync.aligned.m8n8.x4.trans.shared.b16 {%0,%1,%2,%3}, [%4];\n"
                 : "=r"(d[0]), "=r"(d[1]), "=r"(d[2]), "=r"(d[3]) : "r"(addr));
}
__device__ __forceinline__ float ex2(float x) {
    float r;
    asm("ex2.approx.f32 %0, %1;" : "=f"(r) : "f"(x));
    return r;
}
__device__ __forceinline__ uint32_t packbf2(float a, float b) {
    __nv_bfloat162 t = __floats2bfloat162_rn(a, b);
    return *(uint32_t*)&t;
}
__device__ __forceinline__ unsigned short bfbits(float v) {
    bf16 h = __float2bfloat16(v);
    return *(unsigned short*)&h;
}

// ---------------------------------------------------------------------------
// splits
// ---------------------------------------------------------------------------
__global__ void split_rows3(const float* __restrict__ in, bf16* __restrict__ out,
                            int total) {
    int i = blockIdx.x * blockDim.x + threadIdx.x;
    if (i >= total) return;
    float x = in[i];
    bf16 h = __float2bfloat16(x);
    float lo = x - __bfloat162float(h);
    out[3 * i] = h;
    out[3 * i + 1] = h;
    out[3 * i + 2] = __float2bfloat16(lo);
}
// W [K][N] row-major -> out [N][3K], k3 pattern [hi, lo, hi]
__global__ void split_colsT(const float* __restrict__ W, bf16* __restrict__ out,
                            int K, int N) {
    int idx = blockIdx.x * blockDim.x + threadIdx.x;
    if (idx >= N * K) return;
    int n = idx / K, k = idx - n * K;
    float x = W[(size_t)k * N + n];
    bf16 h = __float2bfloat16(x);
    float lo = x - __bfloat162float(h);
    size_t o = (size_t)n * (3 * K) + 3 * k;
    out[o] = h;
    out[o + 1] = __float2bfloat16(lo);
    out[o + 2] = h;
}

// ---------------------------------------------------------------------------
// bf16 GEMM: C(M,N) fp32 = A(M,K) @ Bt(N,K)^T, both K-major bf16.
// CTA tile 128x256, BK=64, 3-stage cp.async (48KB/stage), 256 threads,
// 8 warps each owning a 64x64 microtile.
// ---------------------------------------------------------------------------
#define GBK 64
#define GS 3
#define ST_A (128 * 128)          // 16 KB (128 rows x 128B)
#define ST_B (256 * 128)          // 32 KB
#define ST_BYTES (ST_A + ST_B)    // 48 KB

__global__ __launch_bounds__(256, 1) void bf16gemm(const bf16* __restrict__ A,
                                                   const bf16* __restrict__ Bt,
                                                   float* __restrict__ C,
                                                   int M, int N, int K) {
    extern __shared__ char sm[];
    const uint32_t smBase = (uint32_t)__cvta_generic_to_shared(sm);

    const int tid = threadIdx.x;
    const int warp = tid >> 5, lane = tid & 31;
    const int bm = blockIdx.y, bn = blockIdx.x;
    const int wm = warp >> 2;        // 0..1 -> m offset wm*64
    const int wn = warp & 3;         // 0..3 -> n offset wn*64
    const int KT = K / GBK;

    float acc[4][8][4];
#pragma unroll
    for (int mi = 0; mi < 4; mi++)
#pragma unroll
        for (int ni = 0; ni < 8; ni++)
#pragma unroll
            for (int e = 0; e < 4; e++) acc[mi][ni][e] = 0.f;

    auto load_stage = [&](int sidx, int kt) {
        const uint32_t sb = smBase + sidx * ST_BYTES;
#pragma unroll
        for (int i = 0; i < 12; i++) {
            int q = tid + i * 256;           // 3072 16B chunks
            int r = q >> 3, c = q & 7;
            if (r < 128) {
                const bf16* src = A + (size_t)(bm * 128 + r) * K + kt * GBK + c * 8;
                cp16(sb + r * 128 + (((c ^ (r & 7)) & 7) << 4), src);
            } else {
                int rb = r - 128;
                const bf16* src = Bt + (size_t)(bn * 256 + rb) * K + kt * GBK + c * 8;
                cp16(sb + ST_A + rb * 128 + (((c ^ (rb & 7)) & 7) << 4), src);
            }
        }
    };

    load_stage(0, 0);
    cp_commit();
    load_stage(1, 1);
    cp_commit();

    // per-lane fragment address components
    const int a_row = wm * 64 + (lane & 15);     // + mi*16
    const int a_cl = (lane >> 4);                // chunk low bit
    const int b_rowb = wn * 64 + (lane & 7) + ((lane >> 4) & 1) * 8;  // + np*16
    const int b_cl = ((lane >> 3) & 1);

    int cur = 0;
    for (int kt = 0; kt < KT; kt++) {
        asm volatile("cp.async.wait_group %0;\n" :: "n"(1));
        __syncthreads();
        const uint32_t sb = smBase + cur * ST_BYTES;

#pragma unroll
        for (int ks = 0; ks < 4; ks++) {
            uint32_t af[4][4];
#pragma unroll
            for (int mi = 0; mi < 4; mi++) {
                int row = a_row + mi * 16;
                int c = ks * 2 + a_cl;
                ldsm4(af[mi], sb + row * 128 + (((c ^ (row & 7)) & 7) << 4));
            }
            uint32_t bf_[8][2];
#pragma unroll
            for (int np = 0; np < 4; np++) {
                int row = b_rowb + np * 16;
                int c = ks * 2 + b_cl;
                uint32_t t4[4];
                ldsm4(t4, sb + ST_A + row * 128 + (((c ^ (row & 7)) & 7) << 4));
                bf_[np * 2][0] = t4[0]; bf_[np * 2][1] = t4[1];
                bf_[np * 2 + 1][0] = t4[2]; bf_[np * 2 + 1][1] = t4[3];
            }
#pragma unroll
            for (int mi = 0; mi < 4; mi++)
#pragma unroll
                for (int ni = 0; ni < 8; ni++)
                    mma16816(acc[mi][ni], af[mi], bf_[ni]);
        }

        __syncthreads();
        const int nt = kt + 2;
        if (nt < KT) load_stage(nt % GS, nt);
        cp_commit();
        cur = (cur + 1) % GS;
    }

    // epilogue
#pragma unroll
    for (int mi = 0; mi < 4; mi++) {
        int row = bm * 128 + wm * 64 + mi * 16 + (lane >> 2);
#pragma unroll
        for (int ni = 0; ni < 8; ni++) {
            int col = bn * 256 + wn * 64 + ni * 8 + (lane & 3) * 2;
            *(float2*)&C[(size_t)row * N + col] = make_float2(acc[mi][ni][0], acc[mi][ni][1]);
            *(float2*)&C[(size_t)(row + 8) * N + col] = make_float2(acc[mi][ni][2], acc[mi][ni][3]);
        }
    }
}

// ---------------------------------------------------------------------------
// RoPE + hi/lo split
// ---------------------------------------------------------------------------
__global__ void rope_split(const float* __restrict__ x, int xstride,
                           const float* __restrict__ cosp, const float* __restrict__ sinp,
                           bf16* __restrict__ oh, bf16* __restrict__ ol,
                           int nheads, float scale) {
    int idx = blockIdx.x * blockDim.x + threadIdx.x;
    int total = B_ * T_ * nheads * 64;
    if (idx >= total) return;
    int d = idx & 63;
    int h = (idx >> 6) % nheads;
    int tok = idx / (64 * nheads);
    int t = tok & (T_ - 1);
    size_t ib = (size_t)tok * xstride + h * HD_;
    size_t ob = ((size_t)tok * nheads + h) * HD_;
    float c1 = cosp[t * HD_ + d], s1 = sinp[t * HD_ + d];
    float c2 = cosp[t * HD_ + d + 64], s2 = sinp[t * HD_ + d + 64];
    float x1 = x[ib + d], x2 = x[ib + d + 64];
    float y1 = (x1 * c1 - x2 * s1) * scale;
    float y2 = (x2 * c2 + x1 * s2) * scale;
    bf16 h1 = __float2bfloat16(y1);
    bf16 h2 = __float2bfloat16(y2);
    oh[ob + d] = h1;
    oh[ob + d + 64] = h2;
    ol[ob + d] = __float2bfloat16(y1 - __bfloat162float(h1));
    ol[ob + d + 64] = __float2bfloat16(y2 - __bfloat162float(h2));
}

__global__ void split_hl_kv(const float* __restrict__ in, bf16* __restrict__ oh,
                            bf16* __restrict__ ol, int total) {
    int i = blockIdx.x * blockDim.x + threadIdx.x;
    if (i >= total) return;
    int tok = i >> 9, r = i & 511;
    float x = in[(size_t)tok * 1024 + 512 + r];
    bf16 h = __float2bfloat16(x);
    oh[i] = h;
    ol[i] = __float2bfloat16(x - __bfloat162float(h));
}

// ---------------------------------------------------------------------------
// Tensor-core flash attention (unchanged from R4)
// ---------------------------------------------------------------------------
#define FTILE (64 * 128 * 2)

__global__ __launch_bounds__(128) void flash_mma(const bf16* __restrict__ Qh,
                                                 const bf16* __restrict__ Ql,
                                                 const bf16* __restrict__ Kh,
                                                 const bf16* __restrict__ Kl,
                                                 const bf16* __restrict__ Vh,
                                                 const bf16* __restrict__ Vl,
                                                 bf16* __restrict__ ctxI) {
    extern __shared__ char sm[];
    const uint32_t smBase = (uint32_t)__cvta_generic_to_shared(sm);
    const uint32_t sQh = smBase;
    const uint32_t sQl = smBase + FTILE;
    const uint32_t sKh = smBase + 2 * FTILE;
    const uint32_t sKl = smBase + 3 * FTILE;
    const uint32_t sVh = smBase + 4 * FTILE;
    const uint32_t sVl = smBase + 5 * FTILE;

    const int tid = threadIdx.x;
    const int warp = tid >> 5, lane = tid & 31;
    const int qtile = blockIdx.x;
    const int h = blockIdx.y;
    const int b = blockIdx.z;
    const int kvh = h / (NH_ / KVH_);
    const int q0 = qtile * 64;

    auto loadTile = [&](uint32_t sbase, const bf16* g, size_t gbase, int gstride) {
#pragma unroll
        for (int i = 0; i < 8; i++) {
            int q = tid + i * 128;
            int r = q >> 4, c = q & 15;
            int ch = (c & 8) | ((c ^ (r & 7)) & 7);
            cp16(sbase + r * 256 + (ch << 4), g + gbase + (size_t)r * gstride + c * 8);
        }
    };

    const size_t qgb = ((size_t)(b * T_ + q0) * NH_ + h) * HD_;
    loadTile(sQh, Qh, qgb, NH_ * HD_);
    loadTile(sQl, Ql, qgb, NH_ * HD_);
    cp_commit();

    float oAcc[16][4];
#pragma unroll
    for (int j = 0; j < 16; j++)
#pragma unroll
        for (int e = 0; e < 4; e++) oAcc[j][e] = 0.f;
    float mrow[2] = {-1e30f, -1e30f};
    float lrow[2] = {0.f, 0.f};

    for (int t0 = 0; t0 <= qtile; t0++) {
        const int s0 = t0 * 64;
        __syncthreads();
        const size_t kgb = ((size_t)(b * T_ + s0) * KVH_ + kvh) * HD_;
        loadTile(sKh, Kh, kgb, KVH_ * HD_);
        loadTile(sKl, Kl, kgb, KVH_ * HD_);
        loadTile(sVh, Vh, kgb, KVH_ * HD_);
        loadTile(sVl, Vl, kgb, KVH_ * HD_);
        cp_commit();
        asm volatile("cp.async.wait_group 0;\n" ::);
        __syncthreads();

        float sAcc[8][4];
#pragma unroll
        for (int j = 0; j < 8; j++)
#pragma unroll
            for (int e = 0; e < 4; e++) sAcc[j][e] = 0.f;

#pragma unroll
        for (int ks = 0; ks < 8; ks++) {
            int arow = warp * 16 + (lane & 15);
            int ac = ks * 2 + (lane >> 4);
            int ach = (ac & 8) | ((ac ^ (arow & 7)) & 7);
            uint32_t ah[4], al[4];
            ldsm4(ah, sQh + arow * 256 + (ach << 4));
            ldsm4(al, sQl + arow * 256 + (ach << 4));
            int krow_base = (lane & 7) + ((lane >> 4) & 1) * 8;
            int kc = ks * 2 + ((lane >> 3) & 1);
#pragma unroll
            for (int jp = 0; jp < 4; jp++) {
                int krow = jp * 16 + krow_base;
                int kch = (kc & 8) | ((kc ^ (krow & 7)) & 7);
                uint32_t bh4[4], bl4[4];
                ldsm4(bh4, sKh + krow * 256 + (kch << 4));
                ldsm4(bl4, sKl + krow * 256 + (kch << 4));
                mma16816(sAcc[jp * 2], ah, bh4);
                mma16816(sAcc[jp * 2], ah, bl4);
                mma16816(sAcc[jp * 2], al, bh4);
                mma16816(sAcc[jp * 2 + 1], ah, &bh4[2]);
                mma16816(sAcc[jp * 2 + 1], ah, &bl4[2]);
                mma16816(sAcc[jp * 2 + 1], al, &bh4[2]);
            }
        }

        if (t0 == qtile) {
            int r0 = warp * 16 + (lane >> 2);
#pragma unroll
            for (int j = 0; j < 8; j++) {
                int cb = j * 8 + (lane & 3) * 2;
                if (cb > r0) sAcc[j][0] = -1e30f;
                if (cb + 1 > r0) sAcc[j][1] = -1e30f;
                if (cb > r0 + 8) sAcc[j][2] = -1e30f;
                if (cb + 1 > r0 + 8) sAcc[j][3] = -1e30f;
            }
        }

        float mx0 = -1e30f, mx1 = -1e30f;
#pragma unroll
        for (int j = 0; j < 8; j++) {
            mx0 = fmaxf(mx0, fmaxf(sAcc[j][0], sAcc[j][1]));
            mx1 = fmaxf(mx1, fmaxf(sAcc[j][2], sAcc[j][3]));
        }
        mx0 = fmaxf(mx0, __shfl_xor_sync(0xffffffffu, mx0, 1));
        mx0 = fmaxf(mx0, __shfl_xor_sync(0xffffffffu, mx0, 2));
        mx1 = fmaxf(mx1, __shfl_xor_sync(0xffffffffu, mx1, 1));
        mx1 = fmaxf(mx1, __shfl_xor_sync(0xffffffffu, mx1, 2));
        float mn0 = fmaxf(mrow[0], mx0);
        float mn1 = fmaxf(mrow[1], mx1);
        float al0 = ex2(mrow[0] - mn0);
        float al1 = ex2(mrow[1] - mn1);
        mrow[0] = mn0;
        mrow[1] = mn1;
        float sum0 = 0.f, sum1 = 0.f;
#pragma unroll
        for (int j = 0; j < 8; j++) {
            sAcc[j][0] = ex2(sAcc[j][0] - mn0);
            sAcc[j][1] = ex2(sAcc[j][1] - mn0);
            sAcc[j][2] = ex2(sAcc[j][2] - mn1);
            sAcc[j][3] = ex2(sAcc[j][3] - mn1);
            sum0 += sAcc[j][0] + sAcc[j][1];
            sum1 += sAcc[j][2] + sAcc[j][3];
        }
        sum0 += __shfl_xor_sync(0xffffffffu, sum0, 1);
        sum0 += __shfl_xor_sync(0xffffffffu, sum0, 2);
        sum1 += __shfl_xor_sync(0xffffffffu, sum1, 1);
        sum1 += __shfl_xor_sync(0xffffffffu, sum1, 2);
        lrow[0] = lrow[0] * al0 + sum0;
        lrow[1] = lrow[1] * al1 + sum1;
#pragma unroll
        for (int j = 0; j < 16; j++) {
            oAcc[j][0] *= al0;
            oAcc[j][1] *= al0;
            oAcc[j][2] *= al1;
            oAcc[j][3] *= al1;
        }

        int vrow_b = (lane & 15);
        int vcb = (lane >> 4);
#pragma unroll
        for (int kt = 0; kt < 4; kt++) {
            uint32_t ph[4], pl[4];
            {
                float p0 = sAcc[2 * kt][0], p1 = sAcc[2 * kt][1];
                float p2 = sAcc[2 * kt][2], p3 = sAcc[2 * kt][3];
                float p4 = sAcc[2 * kt + 1][0], p5 = sAcc[2 * kt + 1][1];
                float p6 = sAcc[2 * kt + 1][2], p7 = sAcc[2 * kt + 1][3];
                float h0 = __bfloat162float(__float2bfloat16(p0));
                float h1 = __bfloat162float(__float2bfloat16(p1));
                float h2 = __bfloat162float(__float2bfloat16(p2));
                float h3 = __bfloat162float(__float2bfloat16(p3));
                float h4 = __bfloat162float(__float2bfloat16(p4));
                float h5 = __bfloat162float(__float2bfloat16(p5));
                float h6 = __bfloat162float(__float2bfloat16(p6));
                float h7 = __bfloat162float(__float2bfloat16(p7));
                ph[0] = packbf2(h0, h1); ph[1] = packbf2(h2, h3);
                ph[2] = packbf2(h4, h5); ph[3] = packbf2(h6, h7);
                pl[0] = packbf2(p0 - h0, p1 - h1); pl[1] = packbf2(p2 - h2, p3 - h3);
                pl[2] = packbf2(p4 - h4, p5 - h5); pl[3] = packbf2(p6 - h6, p7 - h7);
            }
            int vrow = kt * 16 + vrow_b;
#pragma unroll
            for (int jp2 = 0; jp2 < 8; jp2++) {
                int vc = jp2 * 2 + vcb;
                int vch = (vc & 8) | ((vc ^ (vrow & 7)) & 7);
                uint32_t vh4[4], vl4[4];
                ldsm4t(vh4, sVh + vrow * 256 + (vch << 4));
                ldsm4t(vl4, sVl + vrow * 256 + (vch << 4));
                mma16816(oAcc[jp2 * 2], ph, vh4);
                mma16816(oAcc[jp2 * 2], ph, vl4);
                mma16816(oAcc[jp2 * 2], pl, vh4);
                mma16816(oAcc[jp2 * 2 + 1], ph, &vh4[2]);
                mma16816(oAcc[jp2 * 2 + 1], ph, &vl4[2]);
                mma16816(oAcc[jp2 * 2 + 1], pl, &vh4[2]);
            }
        }
    }

    float inv0 = 1.f / lrow[0];
    float inv1 = 1.f / lrow[1];
    int r0 = q0 + warp * 16 + (lane >> 2);
    size_t row0 = (size_t)(b * T_ + r0) * (3 * HID_);
    size_t row1 = row0 + (size_t)8 * (3 * HID_);
#pragma unroll
    for (int j = 0; j < 16; j++) {
        int col = h * HD_ + j * 8 + (lane & 3) * 2;
        float v0 = oAcc[j][0] * inv0, v1 = oAcc[j][1] * inv0;
        float v2 = oAcc[j][2] * inv1, v3 = oAcc[j][3] * inv1;
        unsigned short h0 = bfbits(v0), h1 = bfbits(v1);
        unsigned short h2 = bfbits(v2), h3 = bfbits(v3);
        unsigned short l0 = bfbits(v0 - __bfloat162float(__float2bfloat16(v0)));
        unsigned short l1 = bfbits(v1 - __bfloat162float(__float2bfloat16(v1)));
        unsigned short l2 = bfbits(v2 - __bfloat162float(__float2bfloat16(v2)));
        unsigned short l3 = bfbits(v3 - __bfloat162float(__float2bfloat16(v3)));
        uint32_t* p0 = (uint32_t*)(ctxI + row0 + 3 * col);
        p0[0] = (uint32_t)h0 | ((uint32_t)h0 << 16);
        p0[1] = (uint32_t)l0 | ((uint32_t)h1 << 16);
        p0[2] = (uint32_t)h1 | ((uint32_t)l1 << 16);
        uint32_t* p1 = (uint32_t*)(ctxI + row1 + 3 * col);
        p1[0] = (uint32_t)h2 | ((uint32_t)h2 << 16);
        p1[1] = (uint32_t)l2 | ((uint32_t)h3 << 16);
        p1[2] = (uint32_t)h3 | ((uint32_t)l3 << 16);
    }
}

// ---------------------------------------------------------------------------
// Launch
// ---------------------------------------------------------------------------
extern "C" void kernel_launch(void* const* d_in, const int* in_sizes, int n_in,
                              void* d_out, int out_size) {
    const float* hidden = (const float*)d_in[0];
    const float* cosp = (const float*)d_in[2];
    const float* sinp = (const float*)d_in[3];
    const float* Wq = (const float*)d_in[4];
    const float* Wk = (const float*)d_in[5];
    const float* Wv = (const float*)d_in[6];
    const float* Wo = (const float*)d_in[7];
    float* out = (float*)d_out;

    float *q, *kv;
    bf16 *hid_i, *ctx_i, *wq_t, *wkv_t, *wo_t;
    bf16 *qh, *ql, *kh, *kl, *vh, *vl;
    cudaGetSymbolAddress((void**)&q, g_q);
    cudaGetSymbolAddress((void**)&kv, g_kv);
    cudaGetSymbolAddress((void**)&hid_i, g_hid_i);
    cudaGetSymbolAddress((void**)&ctx_i, g_ctx_i);
    cudaGetSymbolAddress((void**)&wq_t, g_wq_t);
    cudaGetSymbolAddress((void**)&wkv_t, g_wkv_t);
    cudaGetSymbolAddress((void**)&wo_t, g_wo_t);
    cudaGetSymbolAddress((void**)&qh, g_qh);
    cudaGetSymbolAddress((void**)&ql, g_ql);
    cudaGetSymbolAddress((void**)&kh, g_kh);
    cudaGetSymbolAddress((void**)&kl, g_kl);
    cudaGetSymbolAddress((void**)&vh, g_vh);
    cudaGetSymbolAddress((void**)&vl, g_vl);

    const int M = B_ * T_;  // 4096

    constexpr int GEMM_SMEM = GS * ST_BYTES;  // 147456
    cudaFuncSetAttribute(bf16gemm, cudaFuncAttributeMaxDynamicSharedMemorySize, GEMM_SMEM);
    cudaFuncSetAttribute(flash_mma, cudaFuncAttributeMaxDynamicSharedMemorySize, 6 * FTILE);

    // input splits
    split_rows3<<<(M * HID_ + 255) / 256, 256>>>(hidden, hid_i, M * HID_);
    split_colsT<<<(2048 * HID_ + 255) / 256, 256>>>(Wq, wq_t, HID_, 2048);
    split_colsT<<<(512 * HID_ + 255) / 256, 256>>>(Wk, wkv_t, HID_, 512);
    split_colsT<<<(512 * HID_ + 255) / 256, 256>>>(Wv, wkv_t + (size_t)512 * K3, HID_, 512);
    split_colsT<<<(2048 * HID_ + 255) / 256, 256>>>(Wo, wo_t, HID_, 2048);

    // projections (mma.sync bf16, 3-term split)
    bf16gemm<<<dim3(2048 / 256, M / 128), 256, GEMM_SMEM>>>(hid_i, wq_t, q, M, 2048, K3);
    bf16gemm<<<dim3(1024 / 256, M / 128), 256, GEMM_SMEM>>>(hid_i, wkv_t, kv, M, 1024, K3);

    // RoPE + hi/lo splits
    const float qscale = 1.4426950408889634f * 0.08838834764831845f;
    rope_split<<<(B_ * T_ * NH_ * 64 + 255) / 256, 256>>>(q, NH_ * HD_, cosp, sinp, qh, ql, NH_, qscale);
    rope_split<<<(B_ * T_ * KVH_ * 64 + 255) / 256, 256>>>(kv, 1024, cosp, sinp, kh, kl, KVH_, 1.0f);
    split_hl_kv<<<(M * 512 + 255) / 256, 256>>>(kv, vh, vl, M * 512);

    // flash attention -> triple-interleaved ctx
    flash_mma<<<dim3(T_ / 64, NH_, B_), 128, 6 * FTILE>>>(qh, ql, kh, kl, vh, vl, ctx_i);

    // output projection
    bf16gemm<<<dim3(2048 / 256, M / 128), 256, GEMM_SMEM>>>(ctx_i, wo_t, out, M, 2048, K3);
}

// round 7
// speedup vs baseline: 1.5857x; 1.5857x over previous
#include <cuda_runtime.h>
#include <cuda_bf16.h>
#include <cstdint>

#define B_ 2
#define T_ 2048
#define HID_ 2048
#define NH_ 16
#define KVH_ 4
#define HD_ 128
#define K3 (3 * HID_)   // 6144
#define NQKV 3072       // fused Q(2048) | K(512) | V(512) output width

typedef __nv_bfloat16 bf16;

// fused QKV GEMM output [4096][3072]
__device__ float g_qkv[(size_t)B_ * T_ * NQKV];
// triple-split GEMM inputs: A row-major [m][3K], B row-major [3K][n]
__device__ bf16 g_hid_i[(size_t)4096 * K3];
__device__ bf16 g_ctx_i[(size_t)4096 * K3];           // written by flash epilogue
__device__ bf16 g_wqkv_i[(size_t)K3 * NQKV];
__device__ bf16 g_wo_i[(size_t)K3 * 2048];
// flash hi/lo inputs
__device__ bf16 g_qh[(size_t)B_ * T_ * NH_ * HD_];
__device__ bf16 g_ql[(size_t)B_ * T_ * NH_ * HD_];
__device__ bf16 g_kh[(size_t)B_ * T_ * KVH_ * HD_];
__device__ bf16 g_kl[(size_t)B_ * T_ * KVH_ * HD_];
__device__ bf16 g_vh[(size_t)B_ * T_ * KVH_ * HD_];
__device__ bf16 g_vl[(size_t)B_ * T_ * KVH_ * HD_];

// ---------------------------------------------------------------------------
// helpers
// ---------------------------------------------------------------------------
__device__ __forceinline__ void cp16(uint32_t s, const void* g) {
    asm volatile("cp.async.cg.shared.global [%0], [%1], 16;\n" :: "r"(s), "l"(g));
}
__device__ __forceinline__ void cp_commit() {
    asm volatile("cp.async.commit_group;\n" ::);
}
__device__ __forceinline__ void mma16816(float* c, const uint32_t* a, const uint32_t* b) {
    asm volatile(
        "mma.sync.aligned.m16n8k16.row.col.f32.bf16.bf16.f32 "
        "{%0,%1,%2,%3}, {%4,%5,%6,%7}, {%8,%9}, {%0,%1,%2,%3};\n"
        : "+f"(c[0]), "+f"(c[1]), "+f"(c[2]), "+f"(c[3])
        : "r"(a[0]), "r"(a[1]), "r"(a[2]), "r"(a[3]), "r"(b[0]), "r"(b[1]));
}
__device__ __forceinline__ void ldsm4(uint32_t* d, uint32_t addr) {
    asm volatile("ldmatrix.sync.aligned.m8n8.x4.shared.b16 {%0,%1,%2,%3}, [%4];\n"
                 : "=r"(d[0]), "=r"(d[1]), "=r"(d[2]), "=r"(d[3]) : "r"(addr));
}
__device__ __forceinline__ void ldsm4t(uint32_t* d, uint32_t addr) {
    asm volatile("ldmatrix.sync.aligned.m8n8.x4.trans.shared.b16 {%0,%1,%2,%3}, [%4];\n"
                 : "=r"(d[0]), "=r"(d[1]), "=r"(d[2]), "=r"(d[3]) : "r"(addr));
}
__device__ __forceinline__ float ex2(float x) {
    float r;
    asm("ex2.approx.f32 %0, %1;" : "=f"(r) : "f"(x));
    return r;
}
__device__ __forceinline__ uint32_t packbf2(float a, float b) {
    __nv_bfloat162 t = __floats2bfloat162_rn(a, b);
    return *(uint32_t*)&t;
}
__device__ __forceinline__ unsigned short bfbits(float v) {
    bf16 h = __float2bfloat16(v);
    return *(unsigned short*)&h;
}

// ---------------------------------------------------------------------------
// splits
// ---------------------------------------------------------------------------
// A-side: [m][K] fp32 -> [m][3K] bf16 pattern [hi,hi,lo]; 8 elems/thread,
// float4 loads, 3 aligned 16B stores.
__global__ void split_rows3v(const float* __restrict__ in, bf16* __restrict__ out,
                             int total8) {
    int i = blockIdx.x * blockDim.x + threadIdx.x;
    if (i >= total8) return;
    float4 x0 = *(const float4*)(in + i * 8);
    float4 x1 = *(const float4*)(in + i * 8 + 4);
    float xs[8] = {x0.x, x0.y, x0.z, x0.w, x1.x, x1.y, x1.z, x1.w};
    unsigned short hb[8], lb[8];
#pragma unroll
    for (int j = 0; j < 8; j++) {
        bf16 h = __float2bfloat16(xs[j]);
        hb[j] = *(unsigned short*)&h;
        bf16 l = __float2bfloat16(xs[j] - __bfloat162float(h));
        lb[j] = *(unsigned short*)&l;
    }
    // 24 bf16: [h0,h0,l0, h1,h1,l1, ...] = 12 uint32
    uint32_t w[12];
#pragma unroll
    for (int j = 0; j < 4; j++) {
        int a = 2 * j, b = 2 * j + 1;
        w[3 * j + 0] = (uint32_t)hb[a] | ((uint32_t)hb[a] << 16);
        w[3 * j + 1] = (uint32_t)lb[a] | ((uint32_t)hb[b] << 16);
        w[3 * j + 2] = (uint32_t)hb[b] | ((uint32_t)lb[b] << 16);
    }
    uint4* dst = (uint4*)(out + (size_t)i * 24);
    dst[0] = make_uint4(w[0], w[1], w[2], w[3]);
    dst[1] = make_uint4(w[4], w[5], w[6], w[7]);
    dst[2] = make_uint4(w[8], w[9], w[10], w[11]);
}

// B-side: W [K][N] row-major -> out [3K][NO] at column offset noff,
// rows 3k=hi, 3k+1=lo, 3k+2=hi. Coalesced reads and writes.
__global__ void split_cols3(const float* __restrict__ W, bf16* __restrict__ out,
                            int K, int N, int NO, int noff) {
    int i = blockIdx.x * blockDim.x + threadIdx.x;
    if (i >= K * N) return;
    int k = i / N, n = i - k * N;
    float x = W[i];
    bf16 h = __float2bfloat16(x);
    float lo = x - __bfloat162float(h);
    size_t base = (size_t)(3 * k) * NO + noff + n;
    out[base] = h;
    out[base + NO] = __float2bfloat16(lo);
    out[base + 2 * (size_t)NO] = h;
}

// ---------------------------------------------------------------------------
// bf16 GEMM (exact R4 config): C(M,N) fp32 = A(M,K) @ B(K,N).
// 128x128x64 tile, 3-stage cp.async, mma.sync m16n8k16, 256 threads,
// warp layout 2(m) x 4(n), warp tile 64x32.
// ---------------------------------------------------------------------------
#define GBM 128
#define GBN 128
#define GBK 64
#define GSTAGES 3
#define A_STAGE_BYTES (GBM * GBK * 2)
#define B_STAGE_BYTES (GBK * GBN * 2)

__global__ __launch_bounds__(256) void bf16gemm(const bf16* __restrict__ A,
                                                const bf16* __restrict__ B,
                                                float* __restrict__ C,
                                                int M, int N, int K) {
    extern __shared__ char sm[];
    const uint32_t smBase = (uint32_t)__cvta_generic_to_shared(sm);
    const uint32_t aBase = smBase;
    const uint32_t bBase = smBase + GSTAGES * A_STAGE_BYTES;

    const int tid = threadIdx.x;
    const int bm = blockIdx.y, bn = blockIdx.x;
    const int warp = tid >> 5, lane = tid & 31;
    const int wm = warp >> 2;
    const int wn = warp & 3;

    float acc[4][4][4];
#pragma unroll
    for (int mi = 0; mi < 4; mi++)
#pragma unroll
        for (int ni = 0; ni < 4; ni++)
#pragma unroll
            for (int e = 0; e < 4; e++) acc[mi][ni][e] = 0.f;

    const int KT = K / GBK;

    auto load_stage = [&](int sidx, int kt) {
#pragma unroll
        for (int i = 0; i < 4; i++) {
            int q = tid + i * 256;
            int r = q >> 3, c = q & 7;
            const bf16* g = A + (size_t)(bm * GBM + r) * K + kt * GBK + c * 8;
            uint32_t s = aBase + sidx * A_STAGE_BYTES + r * 128 + (((c ^ (r & 7)) & 7) << 4);
            cp16(s, g);
        }
#pragma unroll
        for (int i = 0; i < 4; i++) {
            int q = tid + i * 256;
            int r = q >> 4, c = q & 15;
            const bf16* g = B + (size_t)(kt * GBK + r) * N + bn * GBN + c * 8;
            int ch = (c & 8) | ((c ^ (r & 7)) & 7);
            uint32_t s = bBase + sidx * B_STAGE_BYTES + r * 256 + (ch << 4);
            cp16(s, g);
        }
    };

#pragma unroll
    for (int s = 0; s < GSTAGES - 1; s++) {
        load_stage(s, s);
        cp_commit();
    }
    asm volatile("cp.async.wait_group %0;\n" :: "n"(GSTAGES - 2));
    __syncthreads();

    const int a_row = wm * 64 + (lane & 15);
    const int a_col8 = (lane >> 4) * 8;
    const int b_row = (lane & 15);
    const int b_colb = wn * 32 + (lane >> 4) * 8;

    for (int kt = 0; kt < KT; kt++) {
        const int cur = kt % GSTAGES;
        if (kt + GSTAGES - 1 < KT) load_stage((kt + GSTAGES - 1) % GSTAGES, kt + GSTAGES - 1);
        cp_commit();

        const uint32_t aS = aBase + cur * A_STAGE_BYTES;
        const uint32_t bS = bBase + cur * B_STAGE_BYTES;

#pragma unroll
        for (int ks = 0; ks < GBK / 16; ks++) {
            uint32_t af[4][4];
#pragma unroll
            for (int mi = 0; mi < 4; mi++) {
                int row = a_row + mi * 16;
                int col = ks * 16 + a_col8;
                uint32_t addr = aS + row * 128 + ((((col >> 3) ^ (row & 7)) & 7) << 4);
                ldsm4(af[mi], addr);
            }
            uint32_t bfr[4][2];
#pragma unroll
            for (int np = 0; np < 2; np++) {
                int row = ks * 16 + b_row;
                int col = b_colb + np * 16;
                int ch = (col >> 3);
                ch = (ch & 8) | ((ch ^ (row & 7)) & 7);
                uint32_t addr = bS + row * 256 + (ch << 4);
                uint32_t tmp[4];
                ldsm4t(tmp, addr);
                bfr[np * 2][0] = tmp[0]; bfr[np * 2][1] = tmp[1];
                bfr[np * 2 + 1][0] = tmp[2]; bfr[np * 2 + 1][1] = tmp[3];
            }
#pragma unroll
            for (int mi = 0; mi < 4; mi++)
#pragma unroll
                for (int ni = 0; ni < 4; ni++)
                    mma16816(acc[mi][ni], af[mi], bfr[ni]);
        }

        asm volatile("cp.async.wait_group %0;\n" :: "n"(GSTAGES - 2));
        __syncthreads();
    }

#pragma unroll
    for (int mi = 0; mi < 4; mi++) {
#pragma unroll
        for (int ni = 0; ni < 4; ni++) {
            int row = bm * GBM + wm * 64 + mi * 16 + (lane >> 2);
            int col = bn * GBN + wn * 32 + ni * 8 + (lane & 3) * 2;
            *(float2*)&C[(size_t)row * N + col] = make_float2(acc[mi][ni][0], acc[mi][ni][1]);
            *(float2*)&C[(size_t)(row + 8) * N + col] = make_float2(acc[mi][ni][2], acc[mi][ni][3]);
        }
    }
}

// ---------------------------------------------------------------------------
// RoPE + hi/lo split (reads from fused qkv at head offset hoff)
// ---------------------------------------------------------------------------
__global__ void rope_split(const float* __restrict__ x, int xstride, int hoff,
                           const float* __restrict__ cosp, const float* __restrict__ sinp,
                           bf16* __restrict__ oh, bf16* __restrict__ ol,
                           int nheads, float scale) {
    int idx = blockIdx.x * blockDim.x + threadIdx.x;
    int total = B_ * T_ * nheads * 64;
    if (idx >= total) return;
    int d = idx & 63;
    int h = (idx >> 6) % nheads;
    int tok = idx / (64 * nheads);
    int t = tok & (T_ - 1);
    size_t ib = (size_t)tok * xstride + hoff + h * HD_;
    size_t ob = ((size_t)tok * nheads + h) * HD_;
    float c1 = cosp[t * HD_ + d], s1 = sinp[t * HD_ + d];
    float c2 = cosp[t * HD_ + d + 64], s2 = sinp[t * HD_ + d + 64];
    float x1 = x[ib + d], x2 = x[ib + d + 64];
    float y1 = (x1 * c1 - x2 * s1) * scale;
    float y2 = (x2 * c2 + x1 * s2) * scale;
    bf16 h1 = __float2bfloat16(y1);
    bf16 h2 = __float2bfloat16(y2);
    oh[ob + d] = h1;
    oh[ob + d + 64] = h2;
    ol[ob + d] = __float2bfloat16(y1 - __bfloat162float(h1));
    ol[ob + d + 64] = __float2bfloat16(y2 - __bfloat162float(h2));
}

// V slice of fused qkv (cols 2560..3071) -> dense hi/lo
__global__ void split_hl_v(const float* __restrict__ in, bf16* __restrict__ oh,
                           bf16* __restrict__ ol, int total) {
    int i = blockIdx.x * blockDim.x + threadIdx.x;
    if (i >= total) return;
    int tok = i >> 9, r = i & 511;
    float x = in[(size_t)tok * NQKV + 2560 + r];
    bf16 h = __float2bfloat16(x);
    oh[i] = h;
    ol[i] = __float2bfloat16(x - __bfloat162float(h));
}

// ---------------------------------------------------------------------------
// Tensor-core flash attention (exact R4)
// ---------------------------------------------------------------------------
#define FTILE (64 * 128 * 2)

__global__ __launch_bounds__(128) void flash_mma(const bf16* __restrict__ Qh,
                                                 const bf16* __restrict__ Ql,
                                                 const bf16* __restrict__ Kh,
                                                 const bf16* __restrict__ Kl,
                                                 const bf16* __restrict__ Vh,
                                                 const bf16* __restrict__ Vl,
                                                 bf16* __restrict__ ctxI) {
    extern __shared__ char sm[];
    const uint32_t smBase = (uint32_t)__cvta_generic_to_shared(sm);
    const uint32_t sQh = smBase;
    const uint32_t sQl = smBase + FTILE;
    const uint32_t sKh = smBase + 2 * FTILE;
    const uint32_t sKl = smBase + 3 * FTILE;
    const uint32_t sVh = smBase + 4 * FTILE;
    const uint32_t sVl = smBase + 5 * FTILE;

    const int tid = threadIdx.x;
    const int warp = tid >> 5, lane = tid & 31;
    const int qtile = blockIdx.x;
    const int h = blockIdx.y;
    const int b = blockIdx.z;
    const int kvh = h / (NH_ / KVH_);
    const int q0 = qtile * 64;

    auto loadTile = [&](uint32_t sbase, const bf16* g, size_t gbase, int gstride) {
#pragma unroll
        for (int i = 0; i < 8; i++) {
            int q = tid + i * 128;
            int r = q >> 4, c = q & 15;
            int ch = (c & 8) | ((c ^ (r & 7)) & 7);
            cp16(sbase + r * 256 + (ch << 4), g + gbase + (size_t)r * gstride + c * 8);
        }
    };

    const size_t qgb = ((size_t)(b * T_ + q0) * NH_ + h) * HD_;
    loadTile(sQh, Qh, qgb, NH_ * HD_);
    loadTile(sQl, Ql, qgb, NH_ * HD_);
    cp_commit();

    float oAcc[16][4];
#pragma unroll
    for (int j = 0; j < 16; j++)
#pragma unroll
        for (int e = 0; e < 4; e++) oAcc[j][e] = 0.f;
    float mrow[2] = {-1e30f, -1e30f};
    float lrow[2] = {0.f, 0.f};

    for (int t0 = 0; t0 <= qtile; t0++) {
        const int s0 = t0 * 64;
        __syncthreads();
        const size_t kgb = ((size_t)(b * T_ + s0) * KVH_ + kvh) * HD_;
        loadTile(sKh, Kh, kgb, KVH_ * HD_);
        loadTile(sKl, Kl, kgb, KVH_ * HD_);
        loadTile(sVh, Vh, kgb, KVH_ * HD_);
        loadTile(sVl, Vl, kgb, KVH_ * HD_);
        cp_commit();
        asm volatile("cp.async.wait_group 0;\n" ::);
        __syncthreads();

        float sAcc[8][4];
#pragma unroll
        for (int j = 0; j < 8; j++)
#pragma unroll
            for (int e = 0; e < 4; e++) sAcc[j][e] = 0.f;

#pragma unroll
        for (int ks = 0; ks < 8; ks++) {
            int arow = warp * 16 + (lane & 15);
            int ac = ks * 2 + (lane >> 4);
            int ach = (ac & 8) | ((ac ^ (arow & 7)) & 7);
            uint32_t ah[4], al[4];
            ldsm4(ah, sQh + arow * 256 + (ach << 4));
            ldsm4(al, sQl + arow * 256 + (ach << 4));
            int krow_base = (lane & 7) + ((lane >> 4) & 1) * 8;
            int kc = ks * 2 + ((lane >> 3) & 1);
#pragma unroll
            for (int jp = 0; jp < 4; jp++) {
                int krow = jp * 16 + krow_base;
                int kch = (kc & 8) | ((kc ^ (krow & 7)) & 7);
                uint32_t bh4[4], bl4[4];
                ldsm4(bh4, sKh + krow * 256 + (kch << 4));
                ldsm4(bl4, sKl + krow * 256 + (kch << 4));
                mma16816(sAcc[jp * 2], ah, bh4);
                mma16816(sAcc[jp * 2], ah, bl4);
                mma16816(sAcc[jp * 2], al, bh4);
                mma16816(sAcc[jp * 2 + 1], ah, &bh4[2]);
                mma16816(sAcc[jp * 2 + 1], ah, &bl4[2]);
                mma16816(sAcc[jp * 2 + 1], al, &bh4[2]);
            }
        }

        if (t0 == qtile) {
            int r0 = warp * 16 + (lane >> 2);
#pragma unroll
            for (int j = 0; j < 8; j++) {
                int cb = j * 8 + (lane & 3) * 2;
                if (cb > r0) sAcc[j][0] = -1e30f;
                if (cb + 1 > r0) sAcc[j][1] = -1e30f;
                if (cb > r0 + 8) sAcc[j][2] = -1e30f;
                if (cb + 1 > r0 + 8) sAcc[j][3] = -1e30f;
            }
        }

        float mx0 = -1e30f, mx1 = -1e30f;
#pragma unroll
        for (int j = 0; j < 8; j++) {
            mx0 = fmaxf(mx0, fmaxf(sAcc[j][0], sAcc[j][1]));
            mx1 = fmaxf(mx1, fmaxf(sAcc[j][2], sAcc[j][3]));
        }
        mx0 = fmaxf(mx0, __shfl_xor_sync(0xffffffffu, mx0, 1));
        mx0 = fmaxf(mx0, __shfl_xor_sync(0xffffffffu, mx0, 2));
        mx1 = fmaxf(mx1, __shfl_xor_sync(0xffffffffu, mx1, 1));
        mx1 = fmaxf(mx1, __shfl_xor_sync(0xffffffffu, mx1, 2));
        float mn0 = fmaxf(mrow[0], mx0);
        float mn1 = fmaxf(mrow[1], mx1);
        float al0 = ex2(mrow[0] - mn0);
        float al1 = ex2(mrow[1] - mn1);
        mrow[0] = mn0;
        mrow[1] = mn1;
        float sum0 = 0.f, sum1 = 0.f;
#pragma unroll
        for (int j = 0; j < 8; j++) {
            sAcc[j][0] = ex2(sAcc[j][0] - mn0);
            sAcc[j][1] = ex2(sAcc[j][1] - mn0);
            sAcc[j][2] = ex2(sAcc[j][2] - mn1);
            sAcc[j][3] = ex2(sAcc[j][3] - mn1);
            sum0 += sAcc[j][0] + sAcc[j][1];
            sum1 += sAcc[j][2] + sAcc[j][3];
        }
        sum0 += __shfl_xor_sync(0xffffffffu, sum0, 1);
        sum0 += __shfl_xor_sync(0xffffffffu, sum0, 2);
        sum1 += __shfl_xor_sync(0xffffffffu, sum1, 1);
        sum1 += __shfl_xor_sync(0xffffffffu, sum1, 2);
        lrow[0] = lrow[0] * al0 + sum0;
        lrow[1] = lrow[1] * al1 + sum1;
#pragma unroll
        for (int j = 0; j < 16; j++) {
            oAcc[j][0] *= al0;
            oAcc[j][1] *= al0;
            oAcc[j][2] *= al1;
            oAcc[j][3] *= al1;
        }

        int vrow_b = (lane & 15);
        int vcb = (lane >> 4);
#pragma unroll
        for (int kt = 0; kt < 4; kt++) {
            uint32_t ph[4], pl[4];
            {
                float p0 = sAcc[2 * kt][0], p1 = sAcc[2 * kt][1];
                float p2 = sAcc[2 * kt][2], p3 = sAcc[2 * kt][3];
                float p4 = sAcc[2 * kt + 1][0], p5 = sAcc[2 * kt + 1][1];
                float p6 = sAcc[2 * kt + 1][2], p7 = sAcc[2 * kt + 1][3];
                float h0 = __bfloat162float(__float2bfloat16(p0));
                float h1 = __bfloat162float(__float2bfloat16(p1));
                float h2 = __bfloat162float(__float2bfloat16(p2));
                float h3 = __bfloat162float(__float2bfloat16(p3));
                float h4 = __bfloat162float(__float2bfloat16(p4));
                float h5 = __bfloat162float(__float2bfloat16(p5));
                float h6 = __bfloat162float(__float2bfloat16(p6));
                float h7 = __bfloat162float(__float2bfloat16(p7));
                ph[0] = packbf2(h0, h1); ph[1] = packbf2(h2, h3);
                ph[2] = packbf2(h4, h5); ph[3] = packbf2(h6, h7);
                pl[0] = packbf2(p0 - h0, p1 - h1); pl[1] = packbf2(p2 - h2, p3 - h3);
                pl[2] = packbf2(p4 - h4, p5 - h5); pl[3] = packbf2(p6 - h6, p7 - h7);
            }
            int vrow = kt * 16 + vrow_b;
#pragma unroll
            for (int jp2 = 0; jp2 < 8; jp2++) {
                int vc = jp2 * 2 + vcb;
                int vch = (vc & 8) | ((vc ^ (vrow & 7)) & 7);
                uint32_t vh4[4], vl4[4];
                ldsm4t(vh4, sVh + vrow * 256 + (vch << 4));
                ldsm4t(vl4, sVl + vrow * 256 + (vch << 4));
                mma16816(oAcc[jp2 * 2], ph, vh4);
                mma16816(oAcc[jp2 * 2], ph, vl4);
                mma16816(oAcc[jp2 * 2], pl, vh4);
                mma16816(oAcc[jp2 * 2 + 1], ph, &vh4[2]);
                mma16816(oAcc[jp2 * 2 + 1], ph, &vl4[2]);
                mma16816(oAcc[jp2 * 2 + 1], pl, &vh4[2]);
            }
        }
    }

    float inv0 = 1.f / lrow[0];
    float inv1 = 1.f / lrow[1];
    int r0 = q0 + warp * 16 + (lane >> 2);
    size_t row0 = (size_t)(b * T_ + r0) * (3 * HID_);
    size_t row1 = row0 + (size_t)8 * (3 * HID_);
#pragma unroll
    for (int j = 0; j < 16; j++) {
        int col = h * HD_ + j * 8 + (lane & 3) * 2;
        float v0 = oAcc[j][0] * inv0, v1 = oAcc[j][1] * inv0;
        float v2 = oAcc[j][2] * inv1, v3 = oAcc[j][3] * inv1;
        unsigned short h0 = bfbits(v0), h1 = bfbits(v1);
        unsigned short h2 = bfbits(v2), h3 = bfbits(v3);
        unsigned short l0 = bfbits(v0 - __bfloat162float(__float2bfloat16(v0)));
        unsigned short l1 = bfbits(v1 - __bfloat162float(__float2bfloat16(v1)));
        unsigned short l2 = bfbits(v2 - __bfloat162float(__float2bfloat16(v2)));
        unsigned short l3 = bfbits(v3 - __bfloat162float(__float2bfloat16(v3)));
        uint32_t* p0 = (uint32_t*)(ctxI + row0 + 3 * col);
        p0[0] = (uint32_t)h0 | ((uint32_t)h0 << 16);
        p0[1] = (uint32_t)l0 | ((uint32_t)h1 << 16);
        p0[2] = (uint32_t)h1 | ((uint32_t)l1 << 16);
        uint32_t* p1 = (uint32_t*)(ctxI + row1 + 3 * col);
        p1[0] = (uint32_t)h2 | ((uint32_t)h2 << 16);
        p1[1] = (uint32_t)l2 | ((uint32_t)h3 << 16);
        p1[2] = (uint32_t)h3 | ((uint32_t)l3 << 16);
    }
}

// ---------------------------------------------------------------------------
// Launch
// ---------------------------------------------------------------------------
extern "C" void kernel_launch(void* const* d_in, const int* in_sizes, int n_in,
                              void* d_out, int out_size) {
    const float* hidden = (const float*)d_in[0];
    const float* cosp = (const float*)d_in[2];
    const float* sinp = (const float*)d_in[3];
    const float* Wq = (const float*)d_in[4];
    const float* Wk = (const float*)d_in[5];
    const float* Wv = (const float*)d_in[6];
    const float* Wo = (const float*)d_in[7];
    float* out = (float*)d_out;

    float* qkv;
    bf16 *hid_i, *ctx_i, *wqkv_i, *wo_i;
    bf16 *qh, *ql, *kh, *kl, *vh, *vl;
    cudaGetSymbolAddress((void**)&qkv, g_qkv);
    cudaGetSymbolAddress((void**)&hid_i, g_hid_i);
    cudaGetSymbolAddress((void**)&ctx_i, g_ctx_i);
    cudaGetSymbolAddress((void**)&wqkv_i, g_wqkv_i);
    cudaGetSymbolAddress((void**)&wo_i, g_wo_i);
    cudaGetSymbolAddress((void**)&qh, g_qh);
    cudaGetSymbolAddress((void**)&ql, g_ql);
    cudaGetSymbolAddress((void**)&kh, g_kh);
    cudaGetSymbolAddress((void**)&kl, g_kl);
    cudaGetSymbolAddress((void**)&vh, g_vh);
    cudaGetSymbolAddress((void**)&vl, g_vl);

    const int M = B_ * T_;  // 4096

    constexpr int GEMM_SMEM = GSTAGES * (A_STAGE_BYTES + B_STAGE_BYTES);  // 96 KB
    cudaFuncSetAttribute(bf16gemm, cudaFuncAttributeMaxDynamicSharedMemorySize, GEMM_SMEM);
    cudaFuncSetAttribute(flash_mma, cudaFuncAttributeMaxDynamicSharedMemorySize, 6 * FTILE);

    // input splits
    split_rows3v<<<(M * HID_ / 8 + 255) / 256, 256>>>(hidden, hid_i, M * HID_ / 8);
    split_cols3<<<(HID_ * 2048 + 255) / 256, 256>>>(Wq, wqkv_i, HID_, 2048, NQKV, 0);
    split_cols3<<<(HID_ * 512 + 255) / 256, 256>>>(Wk, wqkv_i, HID_, 512, NQKV, 2048);
    split_cols3<<<(HID_ * 512 + 255) / 256, 256>>>(Wv, wqkv_i, HID_, 512, NQKV, 2560);
    split_cols3<<<(HID_ * 2048 + 255) / 256, 256>>>(Wo, wo_i, HID_, 2048, 2048, 0);

    // fused QKV projection (one launch, N=3072)
    bf16gemm<<<dim3(NQKV / GBN, M / GBM), 256, GEMM_SMEM>>>(hid_i, wqkv_i, qkv, M, NQKV, K3);

    // RoPE + hi/lo splits from fused output
    const float qscale = 1.4426950408889634f * 0.08838834764831845f;
    rope_split<<<(B_ * T_ * NH_ * 64 + 255) / 256, 256>>>(qkv, NQKV, 0, cosp, sinp, qh, ql, NH_, qscale);
    rope_split<<<(B_ * T_ * KVH_ * 64 + 255) / 256, 256>>>(qkv, NQKV, 2048, cosp, sinp, kh, kl, KVH_, 1.0f);
    split_hl_v<<<(M * 512 + 255) / 256, 256>>>(qkv, vh, vl, M * 512);

    // flash attention -> triple-interleaved ctx
    flash_mma<<<dim3(T_ / 64, NH_, B_), 128, 6 * FTILE>>>(qh, ql, kh, kl, vh, vl, ctx_i);

    // output projection
    bf16gemm<<<dim3(2048 / GBN, M / GBM), 256, GEMM_SMEM>>>(ctx_i, wo_i, out, M, 2048, K3);
}